// round 1
// baseline (speedup 1.0000x reference)
#include <cuda_runtime.h>
#include <math.h>

// Problem-fixed sizes (from setup_inputs): N=50000, E=1600000, C=64, K=5 (25 kernels)
#define MAXN 50000
#define C 64
#define KK 25

// Scratch: xk [N, 25, 64] = 320MB, hidden h [N,64], agg [N,64]
static __device__ float g_xk[(size_t)MAXN * KK * C];
static __device__ float g_h[(size_t)MAXN * C];
static __device__ float g_agg[(size_t)MAXN * C];

// ---------------------------------------------------------------------------
// atomic float max via monotone int-max / uint-min trick
// ---------------------------------------------------------------------------
__device__ __forceinline__ void atomicMaxFloat(float* addr, float val) {
    int vi = __float_as_int(val);
    if (vi >= 0) {
        atomicMax((int*)addr, vi);
    } else {
        atomicMin((unsigned int*)addr, __float_as_uint(val));
    }
}

// ---------------------------------------------------------------------------
// GEMM: xk[n, k*64+o] = sum_i x[n,i] * W[k,i,o]
// Block: 256 threads, one 64-node tile; loops over all 25 k.
// ---------------------------------------------------------------------------
__global__ void gemm_xk_kernel(const float* __restrict__ x,
                               const float* __restrict__ W,
                               float* __restrict__ xk, int N) {
    __shared__ float xs[64][65];
    __shared__ float ws[64][65];
    const int tid = threadIdx.x;
    const int n0 = blockIdx.x * 64;

    // load x tile (64 nodes x 64 ch)
    for (int t = tid; t < 64 * 64; t += 256) {
        int r = t >> 6, c = t & 63;
        int n = n0 + r;
        xs[r][c] = (n < N) ? x[(size_t)n * C + c] : 0.0f;
    }

    const int ty = tid >> 4;      // 0..15
    const int tx = tid & 15;      // 0..15
    const int row0 = ty * 4;
    const int col0 = tx * 4;

    for (int k = 0; k < KK; ++k) {
        __syncthreads();
        for (int t = tid; t < 64 * 64; t += 256) {
            ws[t >> 6][t & 63] = W[(size_t)k * 4096 + t];
        }
        __syncthreads();

        float acc[4][4];
#pragma unroll
        for (int r = 0; r < 4; ++r)
#pragma unroll
            for (int c = 0; c < 4; ++c) acc[r][c] = 0.0f;

#pragma unroll 16
        for (int i = 0; i < 64; ++i) {
            float a0 = xs[row0 + 0][i];
            float a1 = xs[row0 + 1][i];
            float a2 = xs[row0 + 2][i];
            float a3 = xs[row0 + 3][i];
            float b0 = ws[i][col0 + 0];
            float b1 = ws[i][col0 + 1];
            float b2 = ws[i][col0 + 2];
            float b3 = ws[i][col0 + 3];
            acc[0][0] += a0 * b0; acc[0][1] += a0 * b1; acc[0][2] += a0 * b2; acc[0][3] += a0 * b3;
            acc[1][0] += a1 * b0; acc[1][1] += a1 * b1; acc[1][2] += a1 * b2; acc[1][3] += a1 * b3;
            acc[2][0] += a2 * b0; acc[2][1] += a2 * b1; acc[2][2] += a2 * b2; acc[2][3] += a2 * b3;
            acc[3][0] += a3 * b0; acc[3][1] += a3 * b1; acc[3][2] += a3 * b2; acc[3][3] += a3 * b3;
        }

#pragma unroll
        for (int r = 0; r < 4; ++r) {
            int n = n0 + row0 + r;
            if (n < N) {
                float4 v = make_float4(acc[r][0], acc[r][1], acc[r][2], acc[r][3]);
                *(float4*)&xk[(size_t)n * (KK * C) + k * C + col0] = v;
            }
        }
    }
}

// ---------------------------------------------------------------------------
// Init agg to -inf
// ---------------------------------------------------------------------------
__global__ void init_agg_kernel(float* __restrict__ agg, int total) {
    int i = blockIdx.x * blockDim.x + threadIdx.x;
    if (i < total) agg[i] = -INFINITY;
}

// ---------------------------------------------------------------------------
// Edge kernel: one warp per edge; gather 4 taps from xk[src], weighted sum,
// atomic scatter-max into agg[dst]. Each lane handles 2 channels (float2).
// ---------------------------------------------------------------------------
__global__ void edge_kernel(const float* __restrict__ xk,
                            const int* __restrict__ src,
                            const int* __restrict__ dst,
                            const float* __restrict__ pseudo,
                            float* __restrict__ agg, int E) {
    int warp = (blockIdx.x * blockDim.x + threadIdx.x) >> 5;
    int lane = threadIdx.x & 31;
    if (warp >= E) return;

    int s = src[warp];
    int d = dst[warp];
    float u0 = pseudo[2 * warp + 0];
    float u1 = pseudo[2 * warp + 1];

    float v0 = u0 * 4.0f;   // (K-1) = 4
    float v1 = u1 * 4.0f;
    float b0f = floorf(v0);
    float b1f = floorf(v1);
    float f0 = v0 - b0f;
    float f1 = v1 - b1f;
    int i0 = (int)b0f;
    int i1 = (int)b1f;
    int i0a = min(max(i0, 0), 4);
    int i0b = min(max(i0 + 1, 0), 4);
    int i1a = min(max(i1, 0), 4);
    int i1b = min(max(i1 + 1, 0), 4);

    int   tidx[4] = { i0a + 5 * i1a, i0b + 5 * i1a, i0a + 5 * i1b, i0b + 5 * i1b };
    float tw[4]   = { (1.0f - f0) * (1.0f - f1), f0 * (1.0f - f1),
                      (1.0f - f0) * f1,          f0 * f1 };

    const float* base = xk + (size_t)s * (KK * C);
    float mx = 0.0f, my = 0.0f;
#pragma unroll
    for (int t = 0; t < 4; ++t) {
        float2 v = *(const float2*)(base + tidx[t] * C + lane * 2);
        mx += tw[t] * v.x;
        my += tw[t] * v.y;
    }

    float* aout = agg + (size_t)d * C + lane * 2;
    atomicMaxFloat(aout + 0, mx);
    atomicMaxFloat(aout + 1, my);
}

// ---------------------------------------------------------------------------
// Finalize: out = fix(agg) + x@root + bias, optional relu.
// Block: 256 threads = 64 nodes x 4 channel-groups of 16.
// ---------------------------------------------------------------------------
__global__ void finalize_kernel(const float* __restrict__ agg,
                                const float* __restrict__ xin,
                                const float* __restrict__ root,
                                const float* __restrict__ bias,
                                float* __restrict__ out, int N, int do_relu) {
    __shared__ float rs[64][65];
    __shared__ float xs[64][64];
    const int tid = threadIdx.x;
    const int n0 = blockIdx.x * 64;

    for (int t = tid; t < 4096; t += 256) rs[t >> 6][t & 63] = root[t];
    for (int t = tid; t < 4096; t += 256) {
        int r = t >> 6, c = t & 63;
        int n = n0 + r;
        xs[r][c] = (n < N) ? xin[(size_t)n * C + c] : 0.0f;
    }
    __syncthreads();

    int nl = tid >> 2;            // local node 0..63
    int cg = (tid & 3) * 16;      // channel base
    int n = n0 + nl;
    if (n >= N) return;

    float acc[16];
#pragma unroll
    for (int j = 0; j < 16; ++j) acc[j] = bias[cg + j];

#pragma unroll 8
    for (int i = 0; i < 64; ++i) {
        float xv = xs[nl][i];
#pragma unroll
        for (int j = 0; j < 16; ++j) acc[j] += xv * rs[i][cg + j];
    }

#pragma unroll
    for (int j = 0; j < 16; ++j) {
        float a = agg[(size_t)n * C + cg + j];
        if (!isfinite(a)) a = 0.0f;   // empty segments: -inf -> 0
        float o = a + acc[j];
        if (do_relu) o = fmaxf(o, 0.0f);
        out[(size_t)n * C + cg + j] = o;
    }
}

// ---------------------------------------------------------------------------
// Launch
// ---------------------------------------------------------------------------
extern "C" void kernel_launch(void* const* d_in, const int* in_sizes, int n_in,
                              void* d_out, int out_size) {
    const float* x      = (const float*)d_in[0];
    const int*   ei     = (const int*)  d_in[1];
    const float* pseudo = (const float*)d_in[2];
    const float* W1     = (const float*)d_in[3];
    const float* root1  = (const float*)d_in[4];
    const float* bias1  = (const float*)d_in[5];
    const float* W2     = (const float*)d_in[6];
    const float* root2  = (const float*)d_in[7];
    const float* bias2  = (const float*)d_in[8];

    const int N = in_sizes[0] / C;
    const int E = in_sizes[1] / 2;
    const int* src = ei;
    const int* dst = ei + E;

    float *xk, *h, *agg;
    cudaGetSymbolAddress((void**)&xk,  g_xk);
    cudaGetSymbolAddress((void**)&h,   g_h);
    cudaGetSymbolAddress((void**)&agg, g_agg);

    const int nodeBlocks = (N + 63) / 64;
    const int aggBlocks  = (N * C + 255) / 256;
    const int edgeBlocks = (E + 7) / 8;   // 8 warps per block, one warp per edge

    // ---- Layer 1 ----
    gemm_xk_kernel<<<nodeBlocks, 256>>>(x, W1, xk, N);
    init_agg_kernel<<<aggBlocks, 256>>>(agg, N * C);
    edge_kernel<<<edgeBlocks, 256>>>(xk, src, dst, pseudo, agg, E);
    finalize_kernel<<<nodeBlocks, 256>>>(agg, x, root1, bias1, h, N, 1);

    // ---- Layer 2 ----
    gemm_xk_kernel<<<nodeBlocks, 256>>>(h, W2, xk, N);
    init_agg_kernel<<<aggBlocks, 256>>>(agg, N * C);
    edge_kernel<<<edgeBlocks, 256>>>(xk, src, dst, pseudo, agg, E);
    finalize_kernel<<<nodeBlocks, 256>>>(agg, h, root2, bias2, (float*)d_out, N, 0);
}

// round 2
// speedup vs baseline: 1.6565x; 1.6565x over previous
#include <cuda_runtime.h>
#include <cuda_fp16.h>
#include <math.h>

// Problem-fixed sizes: N=50000, E=1600000, C=64, K=5 (25 kernels)
#define MAXN 50000
#define C 64
#define KK 25

// Scratch: xk [N, 25, 64] fp16 = 160MB, hidden h, agg, rootout fp32
static __device__ __half g_xk[(size_t)MAXN * KK * C];
static __device__ float  g_h[(size_t)MAXN * C];
static __device__ float  g_agg[(size_t)MAXN * C];
static __device__ float  g_root[(size_t)MAXN * C];

// ---------------------------------------------------------------------------
// helpers
// ---------------------------------------------------------------------------
__device__ __forceinline__ unsigned f2tf32(float x) {
    unsigned r;
    asm("cvt.rna.tf32.f32 %0, %1;" : "=r"(r) : "f"(x));
    return r;
}

__device__ __forceinline__ void mma_tf32(float& c0, float& c1, float& c2, float& c3,
                                         unsigned a0, unsigned a1, unsigned a2, unsigned a3,
                                         unsigned b0, unsigned b1) {
    asm("mma.sync.aligned.m16n8k8.row.col.f32.tf32.tf32.f32 "
        "{%0,%1,%2,%3}, {%4,%5,%6,%7}, {%8,%9}, {%0,%1,%2,%3};"
        : "+f"(c0), "+f"(c1), "+f"(c2), "+f"(c3)
        : "r"(a0), "r"(a1), "r"(a2), "r"(a3), "r"(b0), "r"(b1));
}

__device__ __forceinline__ void atomicMaxFloat(float* addr, float val) {
    int vi = __float_as_int(val);
    if (vi >= 0) {
        atomicMax((int*)addr, vi);
    } else {
        atomicMin((unsigned int*)addr, __float_as_uint(val));
    }
}

// ---------------------------------------------------------------------------
// GEMM (tf32 tensor cores): xk[n, k*64+o] = sum_i x[n,i] * W[k,i,o]  (fp16 out)
// plus a 26th matrix (root): rootout[n,o] = sum_i x[n,i]*root[i,o] + bias[o]
// Block: 256 threads (8 warps), one 64-node tile.
// Warp layout: warp>>1 -> m-tile (16 rows), warp&1 -> n-half (32 cols).
// ---------------------------------------------------------------------------
__global__ void gemm_xk_kernel(const float* __restrict__ x,
                               const float* __restrict__ W,
                               const float* __restrict__ root,
                               const float* __restrict__ bias,
                               __half* __restrict__ xk,
                               float* __restrict__ rootout, int N) {
    __shared__ unsigned xs[64][72];   // stride 72: conflict-free B-frag loads
    __shared__ unsigned ws[64][72];
    const int tid  = threadIdx.x;
    const int lane = tid & 31;
    const int warp = tid >> 5;
    const int n0   = blockIdx.x * 64;

    // load + tf32-round x tile (64 nodes x 64 ch)
    for (int t = tid; t < 4096; t += 256) {
        int r = t >> 6, c = t & 63;
        int n = n0 + r;
        float v = (n < N) ? x[(size_t)n * C + c] : 0.0f;
        xs[r][c] = f2tf32(v);
    }
    __syncthreads();

    const int gy = lane >> 2;       // 0..7
    const int gx = lane & 3;        // 0..3
    const int m0 = (warp >> 1) * 16;
    const int nb = (warp & 1) * 32;

    // preload all A fragments (K=64 -> 8 k-steps), reused for all 26 matrices
    unsigned A[8][4];
#pragma unroll
    for (int s = 0; s < 8; ++s) {
        int k0 = s * 8;
        A[s][0] = xs[m0 + gy][k0 + gx];
        A[s][1] = xs[m0 + gy + 8][k0 + gx];
        A[s][2] = xs[m0 + gy][k0 + gx + 4];
        A[s][3] = xs[m0 + gy + 8][k0 + gx + 4];
    }

    const int r0g = n0 + m0 + gy;
    const int r1g = r0g + 8;

    for (int k = 0; k < 26; ++k) {
        const float* src = (k < KK) ? (W + (size_t)k * 4096) : root;
        __syncthreads();
        for (int t = tid; t < 4096; t += 256)
            ws[t >> 6][t & 63] = f2tf32(src[t]);
        __syncthreads();

        float acc[4][4];
#pragma unroll
        for (int t4 = 0; t4 < 4; ++t4)
#pragma unroll
            for (int j = 0; j < 4; ++j) acc[t4][j] = 0.0f;

#pragma unroll
        for (int s = 0; s < 8; ++s) {
            int k0 = s * 8;
#pragma unroll
            for (int t4 = 0; t4 < 4; ++t4) {
                int ncol = nb + t4 * 8;
                unsigned b0 = ws[k0 + gx][ncol + gy];
                unsigned b1 = ws[k0 + gx + 4][ncol + gy];
                mma_tf32(acc[t4][0], acc[t4][1], acc[t4][2], acc[t4][3],
                         A[s][0], A[s][1], A[s][2], A[s][3], b0, b1);
            }
        }

        if (k < KK) {
#pragma unroll
            for (int t4 = 0; t4 < 4; ++t4) {
                int colb = nb + t4 * 8 + gx * 2;
                if (r0g < N) {
                    __half2 h0 = __floats2half2_rn(acc[t4][0], acc[t4][1]);
                    *(__half2*)&xk[(size_t)r0g * (KK * C) + k * C + colb] = h0;
                }
                if (r1g < N) {
                    __half2 h1 = __floats2half2_rn(acc[t4][2], acc[t4][3]);
                    *(__half2*)&xk[(size_t)r1g * (KK * C) + k * C + colb] = h1;
                }
            }
        } else {
#pragma unroll
            for (int t4 = 0; t4 < 4; ++t4) {
                int colb = nb + t4 * 8 + gx * 2;
                float bi0 = bias[colb], bi1 = bias[colb + 1];
                if (r0g < N) {
                    rootout[(size_t)r0g * C + colb]     = acc[t4][0] + bi0;
                    rootout[(size_t)r0g * C + colb + 1] = acc[t4][1] + bi1;
                }
                if (r1g < N) {
                    rootout[(size_t)r1g * C + colb]     = acc[t4][2] + bi0;
                    rootout[(size_t)r1g * C + colb + 1] = acc[t4][3] + bi1;
                }
            }
        }
    }
}

// ---------------------------------------------------------------------------
// Init agg to -inf
// ---------------------------------------------------------------------------
__global__ void init_agg_kernel(float* __restrict__ agg, int total) {
    int i = blockIdx.x * blockDim.x + threadIdx.x;
    if (i < total) agg[i] = -INFINITY;
}

// ---------------------------------------------------------------------------
// Edge kernel: one warp per edge; gather 4 fp16 taps from xk[src] (128B each),
// weighted sum, atomic scatter-max (fp32) into agg[dst]. Lane = 2 channels.
// ---------------------------------------------------------------------------
__global__ void edge_kernel(const __half* __restrict__ xk,
                            const int* __restrict__ src,
                            const int* __restrict__ dst,
                            const float* __restrict__ pseudo,
                            float* __restrict__ agg, int E) {
    int warp = (blockIdx.x * blockDim.x + threadIdx.x) >> 5;
    int lane = threadIdx.x & 31;
    if (warp >= E) return;

    int s = src[warp];
    int d = dst[warp];
    float u0 = pseudo[2 * warp + 0];
    float u1 = pseudo[2 * warp + 1];

    float v0 = u0 * 4.0f;   // (K-1) = 4
    float v1 = u1 * 4.0f;
    float b0f = floorf(v0);
    float b1f = floorf(v1);
    float f0 = v0 - b0f;
    float f1 = v1 - b1f;
    int i0 = (int)b0f;
    int i1 = (int)b1f;
    int i0a = min(max(i0, 0), 4);
    int i0b = min(max(i0 + 1, 0), 4);
    int i1a = min(max(i1, 0), 4);
    int i1b = min(max(i1 + 1, 0), 4);

    int   tidx[4] = { i0a + 5 * i1a, i0b + 5 * i1a, i0a + 5 * i1b, i0b + 5 * i1b };
    float tw[4]   = { (1.0f - f0) * (1.0f - f1), f0 * (1.0f - f1),
                      (1.0f - f0) * f1,          f0 * f1 };

    const __half* base = xk + (size_t)s * (KK * C);
    float mx = 0.0f, my = 0.0f;
#pragma unroll
    for (int t = 0; t < 4; ++t) {
        __half2 hv = *(const __half2*)(base + tidx[t] * C + lane * 2);
        float2 v = __half22float2(hv);
        mx += tw[t] * v.x;
        my += tw[t] * v.y;
    }

    float* aout = agg + (size_t)d * C + lane * 2;
    atomicMaxFloat(aout + 0, mx);
    atomicMaxFloat(aout + 1, my);
}

// ---------------------------------------------------------------------------
// Finalize (elementwise): out = fix(agg) + rootout, optional relu.
// ---------------------------------------------------------------------------
__global__ void finalize_ew_kernel(const float* __restrict__ agg,
                                   const float* __restrict__ rootout,
                                   float* __restrict__ out, int total, int do_relu) {
    int i = blockIdx.x * blockDim.x + threadIdx.x;
    if (i < total) {
        float a = agg[i];
        if (!isfinite(a)) a = 0.0f;     // empty segments: -inf -> 0
        float o = a + rootout[i];
        if (do_relu) o = fmaxf(o, 0.0f);
        out[i] = o;
    }
}

// ---------------------------------------------------------------------------
// Launch
// ---------------------------------------------------------------------------
extern "C" void kernel_launch(void* const* d_in, const int* in_sizes, int n_in,
                              void* d_out, int out_size) {
    const float* x      = (const float*)d_in[0];
    const int*   ei     = (const int*)  d_in[1];
    const float* pseudo = (const float*)d_in[2];
    const float* W1     = (const float*)d_in[3];
    const float* root1  = (const float*)d_in[4];
    const float* bias1  = (const float*)d_in[5];
    const float* W2     = (const float*)d_in[6];
    const float* root2  = (const float*)d_in[7];
    const float* bias2  = (const float*)d_in[8];

    const int N = in_sizes[0] / C;
    const int E = in_sizes[1] / 2;
    const int* src = ei;
    const int* dst = ei + E;

    __half* xk; float *h, *agg, *rootout;
    cudaGetSymbolAddress((void**)&xk,      g_xk);
    cudaGetSymbolAddress((void**)&h,       g_h);
    cudaGetSymbolAddress((void**)&agg,     g_agg);
    cudaGetSymbolAddress((void**)&rootout, g_root);

    const int nodeBlocks = (N + 63) / 64;
    const int ewBlocks   = (N * C + 255) / 256;
    const int edgeBlocks = (E + 7) / 8;   // 8 warps per block, one warp per edge

    // ---- Layer 1 ----
    gemm_xk_kernel<<<nodeBlocks, 256>>>(x, W1, root1, bias1, xk, rootout, N);
    init_agg_kernel<<<ewBlocks, 256>>>(agg, N * C);
    edge_kernel<<<edgeBlocks, 256>>>(xk, src, dst, pseudo, agg, E);
    finalize_ew_kernel<<<ewBlocks, 256>>>(agg, rootout, h, N * C, 1);

    // ---- Layer 2 ----
    gemm_xk_kernel<<<nodeBlocks, 256>>>(h, W2, root2, bias2, xk, rootout, N);
    init_agg_kernel<<<ewBlocks, 256>>>(agg, N * C);
    edge_kernel<<<edgeBlocks, 256>>>(xk, src, dst, pseudo, agg, E);
    finalize_ew_kernel<<<ewBlocks, 256>>>(agg, rootout, (float*)d_out, N * C, 0);
}

// round 3
// speedup vs baseline: 2.3015x; 1.3894x over previous
#include <cuda_runtime.h>
#include <cuda_fp16.h>
#include <math.h>

// Problem-fixed sizes: N=50000, E=1600000, C=64, K=5 (25 kernels)
#define MAXN 50176            // 196*256, padded
#define MAXE 1600000
#define C 64
#define KK 25
#define SCAN_B 1024

// Scratch buffers
static __device__ __half   g_xk[(size_t)MAXN * KK * C];     // 160MB
static __device__ float    g_h[(size_t)MAXN * C];
static __device__ float    g_rootout[(size_t)MAXN * C];
static __device__ unsigned g_wtf1[26 * 4096];               // tf32-rounded W1+root1
static __device__ unsigned g_wtf2[26 * 4096];
static __device__ int      g_deg[MAXN];
static __device__ int      g_cursor[MAXN];
static __device__ int      g_off[MAXN];
static __device__ int      g_offp[MAXN];
static __device__ int      g_bsum[128];
static __device__ int2     g_esrc[MAXE];                    // (src, packed tap idx)
static __device__ float4   g_ew[MAXE];                      // basis weights

// ---------------------------------------------------------------------------
__device__ __forceinline__ unsigned f2tf32(float x) {
    unsigned r;
    asm("cvt.rna.tf32.f32 %0, %1;" : "=r"(r) : "f"(x));
    return r;
}

__device__ __forceinline__ void mma_tf32(float* c,
                                         unsigned a0, unsigned a1, unsigned a2, unsigned a3,
                                         unsigned b0, unsigned b1) {
    asm("mma.sync.aligned.m16n8k8.row.col.f32.tf32.tf32.f32 "
        "{%0,%1,%2,%3}, {%4,%5,%6,%7}, {%8,%9}, {%0,%1,%2,%3};"
        : "+f"(c[0]), "+f"(c[1]), "+f"(c[2]), "+f"(c[3])
        : "r"(a0), "r"(a1), "r"(a2), "r"(a3), "r"(b0), "r"(b1));
}

// ---------------------------------------------------------------------------
// One-time per launch: round W (+root appended as k=25) to tf32 bits
// ---------------------------------------------------------------------------
__global__ void cvt_w_kernel(const float* __restrict__ W, const float* __restrict__ root,
                             unsigned* __restrict__ out) {
    int i = blockIdx.x * blockDim.x + threadIdx.x;
    if (i < 26 * 4096) {
        float v = (i < KK * 4096) ? W[i] : root[i - KK * 4096];
        out[i] = f2tf32(v);
    }
}

// ---------------------------------------------------------------------------
// Edge bucketing: histogram -> scan -> scatter (done once, reused by 2 layers)
// ---------------------------------------------------------------------------
__global__ void zero_kernel(int* __restrict__ deg, int* __restrict__ cur, int N) {
    int i = blockIdx.x * blockDim.x + threadIdx.x;
    if (i < N) { deg[i] = 0; cur[i] = 0; }
}

__global__ void hist_kernel(const int* __restrict__ dst, int* __restrict__ deg, int E) {
    int e = blockIdx.x * blockDim.x + threadIdx.x;
    if (e < E) atomicAdd(&deg[dst[e]], 1);
}

__global__ void scan_local_kernel(const int* __restrict__ deg, int* __restrict__ offp,
                                  int* __restrict__ bsum, int N) {
    __shared__ int s[SCAN_B];
    int tid = threadIdx.x;
    int g = blockIdx.x * SCAN_B + tid;
    int v = (g < N) ? deg[g] : 0;
    s[tid] = v;
    __syncthreads();
#pragma unroll
    for (int o = 1; o < SCAN_B; o <<= 1) {
        int t = (tid >= o) ? s[tid - o] : 0;
        __syncthreads();
        s[tid] += t;
        __syncthreads();
    }
    if (g < N) offp[g] = s[tid] - v;
    if (tid == SCAN_B - 1) bsum[blockIdx.x] = s[tid];
}

__global__ void scan_bsum_kernel(int* __restrict__ bsum, int NB) {
    __shared__ int s[128];
    int tid = threadIdx.x;
    int v = (tid < NB) ? bsum[tid] : 0;
    s[tid] = v;
    __syncthreads();
#pragma unroll
    for (int o = 1; o < 128; o <<= 1) {
        int t = (tid >= o) ? s[tid - o] : 0;
        __syncthreads();
        s[tid] += t;
        __syncthreads();
    }
    if (tid < NB) bsum[tid] = s[tid] - v;   // exclusive
}

__global__ void scan_add_kernel(const int* __restrict__ offp, const int* __restrict__ bsum,
                                int* __restrict__ off, int N) {
    int i = blockIdx.x * blockDim.x + threadIdx.x;
    if (i < N) off[i] = offp[i] + bsum[i / SCAN_B];
}

__global__ void scatter_kernel(const int* __restrict__ src, const int* __restrict__ dst,
                               const float* __restrict__ pseudo,
                               const int* __restrict__ off, int* __restrict__ cur,
                               int2* __restrict__ esrc, float4* __restrict__ ew, int E) {
    int e = blockIdx.x * blockDim.x + threadIdx.x;
    if (e >= E) return;
    int d = dst[e];
    int s = src[e];
    float v0 = pseudo[2 * e + 0] * 4.0f;     // (K-1)=4
    float v1 = pseudo[2 * e + 1] * 4.0f;
    float b0f = floorf(v0), b1f = floorf(v1);
    float f0 = v0 - b0f, f1 = v1 - b1f;
    int i0 = (int)b0f, i1 = (int)b1f;
    int i0a = min(max(i0, 0), 4);
    int i0b = min(max(i0 + 1, 0), 4);
    int i1a = min(max(i1, 0), 4);
    int i1b = min(max(i1 + 1, 0), 4);
    unsigned pk = (unsigned)(i0a + 5 * i1a)
                | ((unsigned)(i0b + 5 * i1a) << 8)
                | ((unsigned)(i0a + 5 * i1b) << 16)
                | ((unsigned)(i0b + 5 * i1b) << 24);
    float4 w = make_float4((1.0f - f0) * (1.0f - f1), f0 * (1.0f - f1),
                           (1.0f - f0) * f1,          f0 * f1);
    int pos = off[d] + atomicAdd(&cur[d], 1);
    esrc[pos] = make_int2(s, (int)pk);
    ew[pos] = w;
}

// ---------------------------------------------------------------------------
// GEMM (tf32 MMA): 256-node tile per block, 26 weight matrices (25 -> xk fp16,
// 26th = root -> rootout fp32 + bias).
// Dynamic smem: xs[256][72] (tf32 x-tile) + ws[64][72] (tf32 W-tile).
// Warp w handles rows [w*32, w*32+32) as two m16 subtiles, all 64 cols.
// ---------------------------------------------------------------------------
__global__ void __launch_bounds__(256, 2)
gemm_xk_kernel(const float* __restrict__ x,
               const unsigned* __restrict__ Wt,   // 26*4096 tf32 bits
               const float* __restrict__ bias,
               __half* __restrict__ xk,
               float* __restrict__ rootout, int N) {
    extern __shared__ unsigned smem[];
    unsigned* xs = smem;                 // [256][72]
    unsigned* ws = smem + 256 * 72;      // [64][72]
    const int tid  = threadIdx.x;
    const int lane = tid & 31;
    const int warp = tid >> 5;
    const int n0   = blockIdx.x * 256;

    // load + tf32-round x tile (256 nodes x 64 ch), float4 vectorized
    for (int t = tid; t < 256 * 16; t += 256) {
        int r = t >> 4, c = (t & 15) * 4;
        int n = n0 + r;
        float4 v = (n < N) ? *(const float4*)&x[(size_t)n * C + c]
                           : make_float4(0.f, 0.f, 0.f, 0.f);
        unsigned* p = &xs[r * 72 + c];
        p[0] = f2tf32(v.x); p[1] = f2tf32(v.y); p[2] = f2tf32(v.z); p[3] = f2tf32(v.w);
    }

    const int gy = lane >> 2;   // 0..7
    const int gx = lane & 3;    // 0..3
    const int m0 = warp * 32;

    for (int k = 0; k < 26; ++k) {
        __syncthreads();
        // load W tile: 1024 uint4
        {
            const uint4* wsrc = (const uint4*)(Wt + (size_t)k * 4096);
            for (int t = tid; t < 1024; t += 256) {
                int r = t >> 4, c = (t & 15) * 4;
                *(uint4*)&ws[r * 72 + c] = wsrc[t];
            }
        }
        __syncthreads();

        float acc[2][8][4];
#pragma unroll
        for (int mt = 0; mt < 2; ++mt)
#pragma unroll
            for (int nt = 0; nt < 8; ++nt)
#pragma unroll
                for (int j = 0; j < 4; ++j) acc[mt][nt][j] = 0.0f;

#pragma unroll
        for (int s = 0; s < 8; ++s) {
            const int k0 = s * 8;
            unsigned a[2][4];
#pragma unroll
            for (int mt = 0; mt < 2; ++mt) {
                int mr = m0 + mt * 16;
                a[mt][0] = xs[(mr + gy)     * 72 + k0 + gx];
                a[mt][1] = xs[(mr + gy + 8) * 72 + k0 + gx];
                a[mt][2] = xs[(mr + gy)     * 72 + k0 + gx + 4];
                a[mt][3] = xs[(mr + gy + 8) * 72 + k0 + gx + 4];
            }
            unsigned b[8][2];
#pragma unroll
            for (int nt = 0; nt < 8; ++nt) {
                b[nt][0] = ws[(k0 + gx)     * 72 + nt * 8 + gy];
                b[nt][1] = ws[(k0 + gx + 4) * 72 + nt * 8 + gy];
            }
#pragma unroll
            for (int mt = 0; mt < 2; ++mt)
#pragma unroll
                for (int nt = 0; nt < 8; ++nt)
                    mma_tf32(acc[mt][nt], a[mt][0], a[mt][1], a[mt][2], a[mt][3],
                             b[nt][0], b[nt][1]);
        }

        if (k < KK) {
#pragma unroll
            for (int mt = 0; mt < 2; ++mt) {
                int r0 = n0 + m0 + mt * 16 + gy;
                int r1 = r0 + 8;
#pragma unroll
                for (int nt = 0; nt < 8; ++nt) {
                    int colb = nt * 8 + gx * 2;
                    if (r0 < N)
                        *(__half2*)&xk[(size_t)r0 * (KK * C) + k * C + colb] =
                            __floats2half2_rn(acc[mt][nt][0], acc[mt][nt][1]);
                    if (r1 < N)
                        *(__half2*)&xk[(size_t)r1 * (KK * C) + k * C + colb] =
                            __floats2half2_rn(acc[mt][nt][2], acc[mt][nt][3]);
                }
            }
        } else {
#pragma unroll
            for (int mt = 0; mt < 2; ++mt) {
                int r0 = n0 + m0 + mt * 16 + gy;
                int r1 = r0 + 8;
#pragma unroll
                for (int nt = 0; nt < 8; ++nt) {
                    int colb = nt * 8 + gx * 2;
                    float bi0 = bias[colb], bi1 = bias[colb + 1];
                    if (r0 < N) {
                        rootout[(size_t)r0 * C + colb]     = acc[mt][nt][0] + bi0;
                        rootout[(size_t)r0 * C + colb + 1] = acc[mt][nt][1] + bi1;
                    }
                    if (r1 < N) {
                        rootout[(size_t)r1 * C + colb]     = acc[mt][nt][2] + bi0;
                        rootout[(size_t)r1 * C + colb + 1] = acc[mt][nt][3] + bi1;
                    }
                }
            }
        }
    }
}

// ---------------------------------------------------------------------------
// Aggregation: one warp per dst node. Iterates its sorted edge list, gathers
// 4 fp16 taps, weighted sum, running max in registers. Fused finalize:
// out = max(+0 if empty) + rootout, optional relu. No atomics.
// ---------------------------------------------------------------------------
__global__ void agg_kernel(const __half* __restrict__ xk,
                           const int2* __restrict__ esrc,
                           const float4* __restrict__ ew,
                           const int* __restrict__ off,
                           const int* __restrict__ deg,
                           const float* __restrict__ rootout,
                           float* __restrict__ out, int N, int do_relu) {
    int node = blockIdx.x * 8 + (threadIdx.x >> 5);
    int lane = threadIdx.x & 31;
    if (node >= N) return;

    int beg = off[node];
    int cnt = deg[node];
    const int c2 = lane * 2;

    float mx = -INFINITY, my = -INFINITY;
#pragma unroll 2
    for (int i = 0; i < cnt; ++i) {
        int2 sp = esrc[beg + i];          // broadcast
        float4 w = ew[beg + i];           // broadcast
        const __half* base = xk + (size_t)sp.x * (KK * C);
        unsigned pk = (unsigned)sp.y;
        float2 v0 = __half22float2(*(const __half2*)(base + (pk & 255u) * C + c2));
        float2 v1 = __half22float2(*(const __half2*)(base + ((pk >> 8) & 255u) * C + c2));
        float2 v2 = __half22float2(*(const __half2*)(base + ((pk >> 16) & 255u) * C + c2));
        float2 v3 = __half22float2(*(const __half2*)(base + (pk >> 24) * C + c2));
        float ex = w.x * v0.x + w.y * v1.x + w.z * v2.x + w.w * v3.x;
        float ey = w.x * v0.y + w.y * v1.y + w.z * v2.y + w.w * v3.y;
        mx = fmaxf(mx, ex);
        my = fmaxf(my, ey);
    }
    if (cnt == 0) { mx = 0.0f; my = 0.0f; }

    float o0 = mx + rootout[(size_t)node * C + c2];
    float o1 = my + rootout[(size_t)node * C + c2 + 1];
    if (do_relu) { o0 = fmaxf(o0, 0.0f); o1 = fmaxf(o1, 0.0f); }
    *(float2*)&out[(size_t)node * C + c2] = make_float2(o0, o1);
}

// ---------------------------------------------------------------------------
// Launch
// ---------------------------------------------------------------------------
extern "C" void kernel_launch(void* const* d_in, const int* in_sizes, int n_in,
                              void* d_out, int out_size) {
    const float* x      = (const float*)d_in[0];
    const int*   ei     = (const int*)  d_in[1];
    const float* pseudo = (const float*)d_in[2];
    const float* W1     = (const float*)d_in[3];
    const float* root1  = (const float*)d_in[4];
    const float* bias1  = (const float*)d_in[5];
    const float* W2     = (const float*)d_in[6];
    const float* root2  = (const float*)d_in[7];
    const float* bias2  = (const float*)d_in[8];

    const int N = in_sizes[0] / C;
    const int E = in_sizes[1] / 2;
    const int* src = ei;
    const int* dst = ei + E;

    __half* xk; float *h, *rootout;
    unsigned *wtf1, *wtf2;
    int *deg, *cur, *off, *offp, *bsum;
    int2* esrc; float4* ew;
    cudaGetSymbolAddress((void**)&xk,      g_xk);
    cudaGetSymbolAddress((void**)&h,       g_h);
    cudaGetSymbolAddress((void**)&rootout, g_rootout);
    cudaGetSymbolAddress((void**)&wtf1,    g_wtf1);
    cudaGetSymbolAddress((void**)&wtf2,    g_wtf2);
    cudaGetSymbolAddress((void**)&deg,     g_deg);
    cudaGetSymbolAddress((void**)&cur,     g_cursor);
    cudaGetSymbolAddress((void**)&off,     g_off);
    cudaGetSymbolAddress((void**)&offp,    g_offp);
    cudaGetSymbolAddress((void**)&bsum,    g_bsum);
    cudaGetSymbolAddress((void**)&esrc,    g_esrc);
    cudaGetSymbolAddress((void**)&ew,      g_ew);

    const int gemmSmem = (256 * 72 + 64 * 72) * 4;   // 92160 B
    static bool attrSet = false;
    if (!attrSet) {
        cudaFuncSetAttribute(gemm_xk_kernel,
                             cudaFuncAttributeMaxDynamicSharedMemorySize, gemmSmem);
        attrSet = true;
    }

    const int NB = (N + SCAN_B - 1) / SCAN_B;
    const int gemmBlocks = (N + 255) / 256;
    const int aggBlocks  = (N + 7) / 8;
    const int eBlocks    = (E + 255) / 256;

    // ---- setup (once, reused by both layers) ----
    cvt_w_kernel<<<(26 * 4096 + 255) / 256, 256>>>(W1, root1, wtf1);
    cvt_w_kernel<<<(26 * 4096 + 255) / 256, 256>>>(W2, root2, wtf2);
    zero_kernel<<<(N + 255) / 256, 256>>>(deg, cur, N);
    hist_kernel<<<eBlocks, 256>>>(dst, deg, E);
    scan_local_kernel<<<NB, SCAN_B>>>(deg, offp, bsum, N);
    scan_bsum_kernel<<<1, 128>>>(bsum, NB);
    scan_add_kernel<<<(N + 255) / 256, 256>>>(offp, bsum, off, N);
    scatter_kernel<<<eBlocks, 256>>>(src, dst, pseudo, off, cur, esrc, ew, E);

    // ---- Layer 1 ----
    gemm_xk_kernel<<<gemmBlocks, 256, gemmSmem>>>(x, wtf1, bias1, xk, rootout, N);
    agg_kernel<<<aggBlocks, 256>>>(xk, esrc, ew, off, deg, rootout, h, N, 1);

    // ---- Layer 2 ----
    gemm_xk_kernel<<<gemmBlocks, 256, gemmSmem>>>(h, wtf2, bias2, xk, rootout, N);
    agg_kernel<<<aggBlocks, 256>>>(xk, esrc, ew, off, deg, rootout, (float*)d_out, N, 0);
}

// round 4
// speedup vs baseline: 2.6656x; 1.1582x over previous
#include <cuda_runtime.h>
#include <cuda_fp16.h>
#include <math.h>

// Problem-fixed sizes: N=50000, E=1600000, C=64, K=5 (25 kernels)
#define MAXN 50176
#define MAXE 1600000
#define C 64
#define KK 25
#define SCAN_B 1024

// Scratch
static __device__ __half g_xk[(size_t)MAXN * KK * C];    // 160MB
static __device__ float  g_h[(size_t)MAXN * C];
static __device__ float  g_rootout[(size_t)MAXN * C];
static __device__ float  g_aggbuf[(size_t)MAXN * C];     // pass-0 partial max
static __device__ __half g_wh1[26 * 4096];               // fp16, transposed [k][o][i]
static __device__ __half g_wh2[26 * 4096];
static __device__ int    g_deg[2 * MAXN];
static __device__ int    g_cursor[2 * MAXN];
static __device__ int    g_off[2 * MAXN];
static __device__ int    g_offp[2 * MAXN];
static __device__ int    g_bsum[128];
static __device__ uint2  g_emeta[MAXE];                  // packed src/taps + half2 frac

// ---------------------------------------------------------------------------
__device__ __forceinline__ void mma_f16(float* c,
                                        unsigned a0, unsigned a1, unsigned a2, unsigned a3,
                                        unsigned b0, unsigned b1) {
    asm("mma.sync.aligned.m16n8k16.row.col.f32.f16.f16.f32 "
        "{%0,%1,%2,%3}, {%4,%5,%6,%7}, {%8,%9}, {%0,%1,%2,%3};"
        : "+f"(c[0]), "+f"(c[1]), "+f"(c[2]), "+f"(c[3])
        : "r"(a0), "r"(a1), "r"(a2), "r"(a3), "r"(b0), "r"(b1));
}

// ---------------------------------------------------------------------------
// One-time: W (+root as k=25) -> fp16, transposed per matrix to [o][i]
// out[k*4096 + o*64 + i] = src[k*4096 + i*64 + o]
// ---------------------------------------------------------------------------
__global__ void cvt_w_kernel(const float* __restrict__ W, const float* __restrict__ root,
                             __half* __restrict__ out) {
    int idx = blockIdx.x * blockDim.x + threadIdx.x;
    if (idx >= 26 * 4096) return;
    int k = idx >> 12, rem = idx & 4095;
    int o = rem >> 6, i = rem & 63;
    int sidx = (k << 12) + i * 64 + o;
    float v = (k < KK) ? W[sidx] : root[i * 64 + o];
    out[idx] = __float2half(v);
}

// ---------------------------------------------------------------------------
// Edge bucketing by (pass, dst): histogram -> scan -> scatter
// pass = (i1a <= 1) ? 0 : 1;  pass0 taps k<15, pass1 taps k>=10
// ---------------------------------------------------------------------------
__device__ __forceinline__ int edge_pass(float u1) {
    float v1 = u1 * 4.0f;
    int i1 = (int)floorf(v1);
    int i1a = min(max(i1, 0), 4);
    return (i1a <= 1) ? 0 : 1;
}

__global__ void zero_kernel(int* __restrict__ deg, int* __restrict__ cur, int total) {
    int i = blockIdx.x * blockDim.x + threadIdx.x;
    if (i < total) { deg[i] = 0; cur[i] = 0; }
}

__global__ void hist_kernel(const int* __restrict__ dst, const float* __restrict__ pseudo,
                            int* __restrict__ deg, int E, int N) {
    int e = blockIdx.x * blockDim.x + threadIdx.x;
    if (e < E) {
        int p = edge_pass(pseudo[2 * e + 1]);
        atomicAdd(&deg[p * N + dst[e]], 1);
    }
}

__global__ void scan_local_kernel(const int* __restrict__ deg, int* __restrict__ offp,
                                  int* __restrict__ bsum, int total) {
    __shared__ int s[SCAN_B];
    int tid = threadIdx.x;
    int g = blockIdx.x * SCAN_B + tid;
    int v = (g < total) ? deg[g] : 0;
    s[tid] = v;
    __syncthreads();
#pragma unroll
    for (int o = 1; o < SCAN_B; o <<= 1) {
        int t = (tid >= o) ? s[tid - o] : 0;
        __syncthreads();
        s[tid] += t;
        __syncthreads();
    }
    if (g < total) offp[g] = s[tid] - v;
    if (tid == SCAN_B - 1) bsum[blockIdx.x] = s[tid];
}

__global__ void scan_bsum_kernel(int* __restrict__ bsum, int NB) {
    __shared__ int s[128];
    int tid = threadIdx.x;
    int v = (tid < NB) ? bsum[tid] : 0;
    s[tid] = v;
    __syncthreads();
#pragma unroll
    for (int o = 1; o < 128; o <<= 1) {
        int t = (tid >= o) ? s[tid - o] : 0;
        __syncthreads();
        s[tid] += t;
        __syncthreads();
    }
    if (tid < NB) bsum[tid] = s[tid] - v;
}

__global__ void scan_add_kernel(const int* __restrict__ offp, const int* __restrict__ bsum,
                                int* __restrict__ off, int total) {
    int i = blockIdx.x * blockDim.x + threadIdx.x;
    if (i < total) off[i] = offp[i] + bsum[i / SCAN_B];
}

__global__ void scatter_kernel(const int* __restrict__ src, const int* __restrict__ dst,
                               const float* __restrict__ pseudo,
                               const int* __restrict__ off, int* __restrict__ cur,
                               uint2* __restrict__ emeta, int E, int N) {
    int e = blockIdx.x * blockDim.x + threadIdx.x;
    if (e >= E) return;
    int d = dst[e];
    int s = src[e];
    float v0 = pseudo[2 * e + 0] * 4.0f;
    float v1 = pseudo[2 * e + 1] * 4.0f;
    float b0f = floorf(v0), b1f = floorf(v1);
    float f0 = v0 - b0f, f1 = v1 - b1f;
    int i0 = (int)b0f, i1 = (int)b1f;
    int i0a = min(max(i0, 0), 4);
    int i0b = min(max(i0 + 1, 0), 4);
    int i1a = min(max(i1, 0), 4);
    int i1b = min(max(i1 + 1, 0), 4);
    int p = (i1a <= 1) ? 0 : 1;

    unsigned w0 = (unsigned)s | ((unsigned)i0a << 17) | ((unsigned)i1a << 20)
                | ((unsigned)(i0b - i0a) << 23) | ((unsigned)(i1b - i1a) << 24);
    __half2 fh = __floats2half2_rn(f0, f1);
    unsigned w1 = *(unsigned*)&fh;

    int pos = off[p * N + d] + atomicAdd(&cur[p * N + d], 1);
    emeta[pos] = make_uint2(w0, w1);
}

// ---------------------------------------------------------------------------
// GEMM (fp16 MMA m16n8k16): 256-node tile, 26 matrices (25 -> xk fp16,
// 26th = root -> rootout fp32 + bias). smem: xs half[256][72], wsT half[64][72]
// (wsT is o-major so B k-pairs are contiguous).
// ---------------------------------------------------------------------------
__global__ void __launch_bounds__(256, 2)
gemm_xk_kernel(const float* __restrict__ x,
               const __half* __restrict__ Wh,   // 26*4096, [k][o][i]
               const float* __restrict__ bias,
               __half* __restrict__ xk,
               float* __restrict__ rootout, int N) {
    extern __shared__ __half smem[];
    __half* xs  = smem;               // [256][72]
    __half* wsT = smem + 256 * 72;    // [64][72], row = o, col = i
    const int tid  = threadIdx.x;
    const int lane = tid & 31;
    const int warp = tid >> 5;
    const int n0   = blockIdx.x * 256;

    // load + fp16-round x tile
    for (int t = tid; t < 256 * 16; t += 256) {
        int r = t >> 4, c = (t & 15) * 4;
        int n = n0 + r;
        float4 v = (n < N) ? *(const float4*)&x[(size_t)n * C + c]
                           : make_float4(0.f, 0.f, 0.f, 0.f);
        __half2* p = (__half2*)&xs[r * 72 + c];
        p[0] = __floats2half2_rn(v.x, v.y);
        p[1] = __floats2half2_rn(v.z, v.w);
    }
    __syncthreads();

    const int gy = lane >> 2;   // 0..7
    const int gx = lane & 3;    // 0..3
    const int m0 = warp * 32;

    // preload A fragments: 4 k-steps x 2 m-tiles x 4 regs, reused for all 26
    unsigned A[4][2][4];
#pragma unroll
    for (int s = 0; s < 4; ++s) {
        int k0 = s * 16;
#pragma unroll
        for (int mt = 0; mt < 2; ++mt) {
            int mr = m0 + mt * 16;
            A[s][mt][0] = *(const unsigned*)&xs[(mr + gy)     * 72 + k0 + 2 * gx];
            A[s][mt][1] = *(const unsigned*)&xs[(mr + gy + 8) * 72 + k0 + 2 * gx];
            A[s][mt][2] = *(const unsigned*)&xs[(mr + gy)     * 72 + k0 + 2 * gx + 8];
            A[s][mt][3] = *(const unsigned*)&xs[(mr + gy + 8) * 72 + k0 + 2 * gx + 8];
        }
    }

    for (int k = 0; k < 26; ++k) {
        __syncthreads();
        {   // W tile: 64 rows(o) x 64 cols(i) halves = 512 uint4
            const uint4* wsrc = (const uint4*)(Wh + (size_t)k * 4096);
            for (int t = tid; t < 512; t += 256) {
                int r = t >> 3, c = (t & 7) * 8;
                *(uint4*)&wsT[r * 72 + c] = wsrc[t];
            }
        }
        __syncthreads();

        float acc[2][8][4];
#pragma unroll
        for (int mt = 0; mt < 2; ++mt)
#pragma unroll
            for (int nt = 0; nt < 8; ++nt)
#pragma unroll
                for (int j = 0; j < 4; ++j) acc[mt][nt][j] = 0.0f;

#pragma unroll
        for (int s = 0; s < 4; ++s) {
            const int k0 = s * 16;
            unsigned b[8][2];
#pragma unroll
            for (int nt = 0; nt < 8; ++nt) {
                int n = nt * 8 + gy;
                b[nt][0] = *(const unsigned*)&wsT[n * 72 + k0 + 2 * gx];
                b[nt][1] = *(const unsigned*)&wsT[n * 72 + k0 + 2 * gx + 8];
            }
#pragma unroll
            for (int mt = 0; mt < 2; ++mt)
#pragma unroll
                for (int nt = 0; nt < 8; ++nt)
                    mma_f16(acc[mt][nt], A[s][mt][0], A[s][mt][1], A[s][mt][2], A[s][mt][3],
                            b[nt][0], b[nt][1]);
        }

        if (k < KK) {
#pragma unroll
            for (int mt = 0; mt < 2; ++mt) {
                int r0 = n0 + m0 + mt * 16 + gy;
                int r1 = r0 + 8;
#pragma unroll
                for (int nt = 0; nt < 8; ++nt) {
                    int colb = nt * 8 + gx * 2;
                    if (r0 < N)
                        *(__half2*)&xk[(size_t)r0 * (KK * C) + k * C + colb] =
                            __floats2half2_rn(acc[mt][nt][0], acc[mt][nt][1]);
                    if (r1 < N)
                        *(__half2*)&xk[(size_t)r1 * (KK * C) + k * C + colb] =
                            __floats2half2_rn(acc[mt][nt][2], acc[mt][nt][3]);
                }
            }
        } else {
#pragma unroll
            for (int mt = 0; mt < 2; ++mt) {
                int r0 = n0 + m0 + mt * 16 + gy;
                int r1 = r0 + 8;
#pragma unroll
                for (int nt = 0; nt < 8; ++nt) {
                    int colb = nt * 8 + gx * 2;
                    float bi0 = bias[colb], bi1 = bias[colb + 1];
                    if (r0 < N) {
                        rootout[(size_t)r0 * C + colb]     = acc[mt][nt][0] + bi0;
                        rootout[(size_t)r0 * C + colb + 1] = acc[mt][nt][1] + bi1;
                    }
                    if (r1 < N) {
                        rootout[(size_t)r1 * C + colb]     = acc[mt][nt][2] + bi0;
                        rootout[(size_t)r1 * C + colb + 1] = acc[mt][nt][3] + bi1;
                    }
                }
            }
        }
    }
}

// ---------------------------------------------------------------------------
// Aggregation pass: one warp per dst node, software-pipelined gathers.
// mode 0: partial max -> aggbuf (raw, may be -inf)
// mode 1: combine with aggbuf, fix empty->0, + rootout, opt relu -> out
// ---------------------------------------------------------------------------
__global__ void agg_kernel(const __half* __restrict__ xk,
                           const uint2* __restrict__ emeta,
                           const int* __restrict__ off,
                           const int* __restrict__ deg,
                           const float* __restrict__ aggbuf,
                           const float* __restrict__ rootout,
                           float* __restrict__ out, int N,
                           int mode, int do_relu) {
    int node = blockIdx.x * 8 + (threadIdx.x >> 5);
    int lane = threadIdx.x & 31;
    if (node >= N) return;

    int beg = off[node];
    int cnt = deg[node];
    const int c2 = lane * 2;

    float prevx = -INFINITY, prevy = -INFINITY;
    if (mode == 1) {
        float2 p = *(const float2*)&aggbuf[(size_t)node * C + c2];
        prevx = p.x; prevy = p.y;
    }
    float mx = prevx, my = prevy;

    if (cnt > 0) {
        const __half* xkl = xk + c2;
        uint2 m = emeta[beg];
        // stage regs
        __half2 v00, v01, v10, v11;
        {
            unsigned w = m.x;
            int s   = w & 131071;
            int i0a = (w >> 17) & 7, i1a = (w >> 20) & 7;
            int dx  = (w >> 23) & 1, dy  = (w >> 24) & 1;
            int t00 = i0a + 5 * i1a;
            const __half* base = xkl + (size_t)s * (KK * C);
            v00 = *(const __half2*)(base + t00 * C);
            v01 = *(const __half2*)(base + (t00 + dx) * C);
            v10 = *(const __half2*)(base + (t00 + 5 * dy) * C);
            v11 = *(const __half2*)(base + (t00 + 5 * dy + dx) * C);
        }
        for (int i = 1; i < cnt; ++i) {
            uint2 m2 = emeta[beg + i];
            __half2 u00, u01, u10, u11;
            {
                unsigned w = m2.x;
                int s   = w & 131071;
                int i0a = (w >> 17) & 7, i1a = (w >> 20) & 7;
                int dx  = (w >> 23) & 1, dy  = (w >> 24) & 1;
                int t00 = i0a + 5 * i1a;
                const __half* base = xkl + (size_t)s * (KK * C);
                u00 = *(const __half2*)(base + t00 * C);
                u01 = *(const __half2*)(base + (t00 + dx) * C);
                u10 = *(const __half2*)(base + (t00 + 5 * dy) * C);
                u11 = *(const __half2*)(base + (t00 + 5 * dy + dx) * C);
            }
            {   // consume stage A
                float2 f = __half22float2(*(__half2*)&m.y);
                float w00 = (1.0f - f.x) * (1.0f - f.y);
                float w01 = f.x * (1.0f - f.y);
                float w10 = (1.0f - f.x) * f.y;
                float w11 = f.x * f.y;
                float2 a0 = __half22float2(v00), a1 = __half22float2(v01);
                float2 a2 = __half22float2(v10), a3 = __half22float2(v11);
                float ex = w00 * a0.x + w01 * a1.x + w10 * a2.x + w11 * a3.x;
                float ey = w00 * a0.y + w01 * a1.y + w10 * a2.y + w11 * a3.y;
                mx = fmaxf(mx, ex); my = fmaxf(my, ey);
            }
            m = m2; v00 = u00; v01 = u01; v10 = u10; v11 = u11;
        }
        {   // final consume
            float2 f = __half22float2(*(__half2*)&m.y);
            float w00 = (1.0f - f.x) * (1.0f - f.y);
            float w01 = f.x * (1.0f - f.y);
            float w10 = (1.0f - f.x) * f.y;
            float w11 = f.x * f.y;
            float2 a0 = __half22float2(v00), a1 = __half22float2(v01);
            float2 a2 = __half22float2(v10), a3 = __half22float2(v11);
            float ex = w00 * a0.x + w01 * a1.x + w10 * a2.x + w11 * a3.x;
            float ey = w00 * a0.y + w01 * a1.y + w10 * a2.y + w11 * a3.y;
            mx = fmaxf(mx, ex); my = fmaxf(my, ey);
        }
    }

    if (mode == 0) {
        *(float2*)&out[(size_t)node * C + c2] = make_float2(mx, my);
    } else {
        if (!isfinite(mx)) mx = 0.0f;
        if (!isfinite(my)) my = 0.0f;
        float2 r = *(const float2*)&rootout[(size_t)node * C + c2];
        float o0 = mx + r.x, o1 = my + r.y;
        if (do_relu) { o0 = fmaxf(o0, 0.0f); o1 = fmaxf(o1, 0.0f); }
        *(float2*)&out[(size_t)node * C + c2] = make_float2(o0, o1);
    }
}

// ---------------------------------------------------------------------------
extern "C" void kernel_launch(void* const* d_in, const int* in_sizes, int n_in,
                              void* d_out, int out_size) {
    const float* x      = (const float*)d_in[0];
    const int*   ei     = (const int*)  d_in[1];
    const float* pseudo = (const float*)d_in[2];
    const float* W1     = (const float*)d_in[3];
    const float* root1  = (const float*)d_in[4];
    const float* bias1  = (const float*)d_in[5];
    const float* W2     = (const float*)d_in[6];
    const float* root2  = (const float*)d_in[7];
    const float* bias2  = (const float*)d_in[8];

    const int N = in_sizes[0] / C;
    const int E = in_sizes[1] / 2;
    const int* src = ei;
    const int* dst = ei + E;

    __half *xk, *wh1, *wh2;
    float *h, *rootout, *aggbuf;
    int *deg, *cur, *off, *offp, *bsum;
    uint2* emeta;
    cudaGetSymbolAddress((void**)&xk,      g_xk);
    cudaGetSymbolAddress((void**)&h,       g_h);
    cudaGetSymbolAddress((void**)&rootout, g_rootout);
    cudaGetSymbolAddress((void**)&aggbuf,  g_aggbuf);
    cudaGetSymbolAddress((void**)&wh1,     g_wh1);
    cudaGetSymbolAddress((void**)&wh2,     g_wh2);
    cudaGetSymbolAddress((void**)&deg,     g_deg);
    cudaGetSymbolAddress((void**)&cur,     g_cursor);
    cudaGetSymbolAddress((void**)&off,     g_off);
    cudaGetSymbolAddress((void**)&offp,    g_offp);
    cudaGetSymbolAddress((void**)&bsum,    g_bsum);
    cudaGetSymbolAddress((void**)&emeta,   g_emeta);

    const int gemmSmem = (256 * 72 + 64 * 72) * 2;   // 46080 B (fp16)
    const int total2N  = 2 * N;
    const int NB = (total2N + SCAN_B - 1) / SCAN_B;
    const int gemmBlocks = (N + 255) / 256;
    const int aggBlocks  = (N + 7) / 8;
    const int eBlocks    = (E + 255) / 256;

    // ---- setup (once, reused by both layers) ----
    cvt_w_kernel<<<(26 * 4096 + 255) / 256, 256>>>(W1, root1, wh1);
    cvt_w_kernel<<<(26 * 4096 + 255) / 256, 256>>>(W2, root2, wh2);
    zero_kernel<<<(total2N + 255) / 256, 256>>>(deg, cur, total2N);
    hist_kernel<<<eBlocks, 256>>>(dst, pseudo, deg, E, N);
    scan_local_kernel<<<NB, SCAN_B>>>(deg, offp, bsum, total2N);
    scan_bsum_kernel<<<1, 128>>>(bsum, NB);
    scan_add_kernel<<<(total2N + 255) / 256, 256>>>(offp, bsum, off, total2N);
    scatter_kernel<<<eBlocks, 256>>>(src, dst, pseudo, off, cur, emeta, E, N);

    // ---- Layer 1 ----
    gemm_xk_kernel<<<gemmBlocks, 256, gemmSmem>>>(x, wh1, bias1, xk, rootout, N);
    agg_kernel<<<aggBlocks, 256>>>(xk, emeta, off,     deg,     aggbuf, rootout, aggbuf, N, 0, 0);
    agg_kernel<<<aggBlocks, 256>>>(xk, emeta, off + N, deg + N, aggbuf, rootout, h,      N, 1, 1);

    // ---- Layer 2 ----
    gemm_xk_kernel<<<gemmBlocks, 256, gemmSmem>>>(h, wh2, bias2, xk, rootout, N);
    agg_kernel<<<aggBlocks, 256>>>(xk, emeta, off,     deg,     aggbuf, rootout, aggbuf, N, 0, 0);
    agg_kernel<<<aggBlocks, 256>>>(xk, emeta, off + N, deg + N, aggbuf, rootout, (float*)d_out, N, 1, 0);
}

// round 5
// speedup vs baseline: 2.7747x; 1.0409x over previous
#include <cuda_runtime.h>
#include <cuda_fp16.h>
#include <math.h>

// Problem-fixed sizes: N=50000, E=1600000, C=64, K=5 (25 kernels)
#define MAXN 50176
#define MAXE 1600000
#define C 64
#define KK 25
#define SCAN_B 1024

// Scratch
static __device__ __half g_xk[(size_t)MAXN * KK * C];    // 160MB
static __device__ float  g_h[(size_t)MAXN * C];
static __device__ float  g_rootout[(size_t)MAXN * C];
static __device__ float  g_aggbuf[(size_t)MAXN * C];     // pass-0 partial max
static __device__ uint2  g_wf1[26 * 4 * 8 * 32];         // W1+root1 in MMA-frag order
static __device__ uint2  g_wf2[26 * 4 * 8 * 32];
static __device__ int    g_deg[2 * MAXN];
static __device__ int    g_cursor[2 * MAXN];
static __device__ int    g_off[2 * MAXN];
static __device__ int    g_offp[2 * MAXN];
static __device__ int    g_bsum[128];
static __device__ uint2  g_emeta[MAXE];                  // packed src/taps + half2 frac

// ---------------------------------------------------------------------------
__device__ __forceinline__ void mma_f16(float* c,
                                        unsigned a0, unsigned a1, unsigned a2, unsigned a3,
                                        unsigned b0, unsigned b1) {
    asm("mma.sync.aligned.m16n8k16.row.col.f32.f16.f16.f32 "
        "{%0,%1,%2,%3}, {%4,%5,%6,%7}, {%8,%9}, {%0,%1,%2,%3};"
        : "+f"(c[0]), "+f"(c[1]), "+f"(c[2]), "+f"(c[3])
        : "r"(a0), "r"(a1), "r"(a2), "r"(a3), "r"(b0), "r"(b1));
}

// ---------------------------------------------------------------------------
// One-time: W (+root as k=25) -> fp16 B-fragments in MMA lane order.
// frag[((k*4+s)*8+nt)*32 + lane] = {half2(W[i][o],W[i+1][o]), half2(W[i+8][o],W[i+9][o])}
// with o = nt*8 + (lane>>2), i = s*16 + 2*(lane&3).
// ---------------------------------------------------------------------------
__global__ void cvt_w_kernel(const float* __restrict__ W, const float* __restrict__ root,
                             uint2* __restrict__ frag) {
    int idx = blockIdx.x * blockDim.x + threadIdx.x;
    if (idx >= 26 * 4 * 8 * 32) return;
    int lane = idx & 31;
    int nt   = (idx >> 5) & 7;
    int s    = (idx >> 8) & 3;
    int k    = idx >> 10;
    int gy = lane >> 2, gx = lane & 3;
    int o = nt * 8 + gy;
    int i = s * 16 + 2 * gx;
    const float* src = (k < KK) ? (W + (size_t)k * 4096) : root;
    __half2 b0 = __floats2half2_rn(src[i * 64 + o],       src[(i + 1) * 64 + o]);
    __half2 b1 = __floats2half2_rn(src[(i + 8) * 64 + o], src[(i + 9) * 64 + o]);
    frag[idx] = make_uint2(*(unsigned*)&b0, *(unsigned*)&b1);
}

// ---------------------------------------------------------------------------
// Edge bucketing by (pass, dst): histogram -> scan -> scatter
// pass = (i1a <= 1) ? 0 : 1;  pass0 taps k<15, pass1 taps k>=10
// ---------------------------------------------------------------------------
__device__ __forceinline__ int edge_pass(float u1) {
    float v1 = u1 * 4.0f;
    int i1 = (int)floorf(v1);
    int i1a = min(max(i1, 0), 4);
    return (i1a <= 1) ? 0 : 1;
}

__global__ void zero_kernel(int* __restrict__ deg, int* __restrict__ cur, int total) {
    int i = blockIdx.x * blockDim.x + threadIdx.x;
    if (i < total) { deg[i] = 0; cur[i] = 0; }
}

__global__ void hist_kernel(const int* __restrict__ dst, const float* __restrict__ pseudo,
                            int* __restrict__ deg, int E, int N) {
    int e = blockIdx.x * blockDim.x + threadIdx.x;
    if (e < E) {
        int p = edge_pass(pseudo[2 * e + 1]);
        atomicAdd(&deg[p * N + dst[e]], 1);
    }
}

__global__ void scan_local_kernel(const int* __restrict__ deg, int* __restrict__ offp,
                                  int* __restrict__ bsum, int total) {
    __shared__ int s[SCAN_B];
    int tid = threadIdx.x;
    int g = blockIdx.x * SCAN_B + tid;
    int v = (g < total) ? deg[g] : 0;
    s[tid] = v;
    __syncthreads();
#pragma unroll
    for (int o = 1; o < SCAN_B; o <<= 1) {
        int t = (tid >= o) ? s[tid - o] : 0;
        __syncthreads();
        s[tid] += t;
        __syncthreads();
    }
    if (g < total) offp[g] = s[tid] - v;
    if (tid == SCAN_B - 1) bsum[blockIdx.x] = s[tid];
}

__global__ void scan_bsum_kernel(int* __restrict__ bsum, int NB) {
    __shared__ int s[128];
    int tid = threadIdx.x;
    int v = (tid < NB) ? bsum[tid] : 0;
    s[tid] = v;
    __syncthreads();
#pragma unroll
    for (int o = 1; o < 128; o <<= 1) {
        int t = (tid >= o) ? s[tid - o] : 0;
        __syncthreads();
        s[tid] += t;
        __syncthreads();
    }
    if (tid < NB) bsum[tid] = s[tid] - v;
}

__global__ void scan_add_kernel(const int* __restrict__ offp, const int* __restrict__ bsum,
                                int* __restrict__ off, int total) {
    int i = blockIdx.x * blockDim.x + threadIdx.x;
    if (i < total) off[i] = offp[i] + bsum[i / SCAN_B];
}

__global__ void scatter_kernel(const int* __restrict__ src, const int* __restrict__ dst,
                               const float* __restrict__ pseudo,
                               const int* __restrict__ off, int* __restrict__ cur,
                               uint2* __restrict__ emeta, int E, int N) {
    int e = blockIdx.x * blockDim.x + threadIdx.x;
    if (e >= E) return;
    int d = dst[e];
    int s = src[e];
    float v0 = pseudo[2 * e + 0] * 4.0f;
    float v1 = pseudo[2 * e + 1] * 4.0f;
    float b0f = floorf(v0), b1f = floorf(v1);
    float f0 = v0 - b0f, f1 = v1 - b1f;
    int i0 = (int)b0f, i1 = (int)b1f;
    int i0a = min(max(i0, 0), 4);
    int i0b = min(max(i0 + 1, 0), 4);
    int i1a = min(max(i1, 0), 4);
    int i1b = min(max(i1 + 1, 0), 4);
    int p = (i1a <= 1) ? 0 : 1;

    unsigned w0 = (unsigned)s | ((unsigned)i0a << 17) | ((unsigned)i1a << 20)
                | ((unsigned)(i0b - i0a) << 23) | ((unsigned)(i1b - i1a) << 24);
    __half2 fh = __floats2half2_rn(f0, f1);
    unsigned w1 = *(unsigned*)&fh;

    int pos = off[p * N + d] + atomicAdd(&cur[p * N + d], 1);
    emeta[pos] = make_uint2(w0, w1);
}

// ---------------------------------------------------------------------------
// GEMM (fp16 MMA m16n8k16): 256-node tile, 26 matrices. No smem for W:
// B fragments loaded directly from pre-packed global (L1-resident after warp 0).
// A fragments register-resident for all 26 matrices. One __syncthreads total.
// ---------------------------------------------------------------------------
__global__ void __launch_bounds__(256, 2)
gemm_xk_kernel(const float* __restrict__ x,
               const uint2* __restrict__ Wf,    // 26*4*8*32 frag order
               const float* __restrict__ bias,
               __half* __restrict__ xk,
               float* __restrict__ rootout, int N) {
    __shared__ __half xs[256 * 72];
    const int tid  = threadIdx.x;
    const int lane = tid & 31;
    const int warp = tid >> 5;
    const int n0   = blockIdx.x * 256;

    for (int t = tid; t < 256 * 16; t += 256) {
        int r = t >> 4, c = (t & 15) * 4;
        int n = n0 + r;
        float4 v = (n < N) ? *(const float4*)&x[(size_t)n * C + c]
                           : make_float4(0.f, 0.f, 0.f, 0.f);
        __half2* p = (__half2*)&xs[r * 72 + c];
        p[0] = __floats2half2_rn(v.x, v.y);
        p[1] = __floats2half2_rn(v.z, v.w);
    }
    __syncthreads();

    const int gy = lane >> 2;
    const int gx = lane & 3;
    const int m0 = warp * 32;

    unsigned A[4][2][4];
#pragma unroll
    for (int s = 0; s < 4; ++s) {
        int k0 = s * 16;
#pragma unroll
        for (int mt = 0; mt < 2; ++mt) {
            int mr = m0 + mt * 16;
            A[s][mt][0] = *(const unsigned*)&xs[(mr + gy)     * 72 + k0 + 2 * gx];
            A[s][mt][1] = *(const unsigned*)&xs[(mr + gy + 8) * 72 + k0 + 2 * gx];
            A[s][mt][2] = *(const unsigned*)&xs[(mr + gy)     * 72 + k0 + 2 * gx + 8];
            A[s][mt][3] = *(const unsigned*)&xs[(mr + gy + 8) * 72 + k0 + 2 * gx + 8];
        }
    }

    for (int k = 0; k < 26; ++k) {
        const uint2* wf = Wf + (size_t)k * 1024 + lane;

        float acc[2][8][4];
#pragma unroll
        for (int mt = 0; mt < 2; ++mt)
#pragma unroll
            for (int nt = 0; nt < 8; ++nt)
#pragma unroll
                for (int j = 0; j < 4; ++j) acc[mt][nt][j] = 0.0f;

#pragma unroll
        for (int s = 0; s < 4; ++s) {
            uint2 b[8];
#pragma unroll
            for (int nt = 0; nt < 8; ++nt)
                b[nt] = wf[(s * 8 + nt) * 32];
#pragma unroll
            for (int nt = 0; nt < 8; ++nt) {
                mma_f16(acc[0][nt], A[s][0][0], A[s][0][1], A[s][0][2], A[s][0][3],
                        b[nt].x, b[nt].y);
                mma_f16(acc[1][nt], A[s][1][0], A[s][1][1], A[s][1][2], A[s][1][3],
                        b[nt].x, b[nt].y);
            }
        }

        if (k < KK) {
#pragma unroll
            for (int mt = 0; mt < 2; ++mt) {
                int r0 = n0 + m0 + mt * 16 + gy;
                int r1 = r0 + 8;
#pragma unroll
                for (int nt = 0; nt < 8; ++nt) {
                    int colb = nt * 8 + gx * 2;
                    if (r0 < N)
                        *(__half2*)&xk[(size_t)r0 * (KK * C) + k * C + colb] =
                            __floats2half2_rn(acc[mt][nt][0], acc[mt][nt][1]);
                    if (r1 < N)
                        *(__half2*)&xk[(size_t)r1 * (KK * C) + k * C + colb] =
                            __floats2half2_rn(acc[mt][nt][2], acc[mt][nt][3]);
                }
            }
        } else {
#pragma unroll
            for (int mt = 0; mt < 2; ++mt) {
                int r0 = n0 + m0 + mt * 16 + gy;
                int r1 = r0 + 8;
#pragma unroll
                for (int nt = 0; nt < 8; ++nt) {
                    int colb = nt * 8 + gx * 2;
                    float bi0 = bias[colb], bi1 = bias[colb + 1];
                    if (r0 < N) {
                        rootout[(size_t)r0 * C + colb]     = acc[mt][nt][0] + bi0;
                        rootout[(size_t)r0 * C + colb + 1] = acc[mt][nt][1] + bi1;
                    }
                    if (r1 < N) {
                        rootout[(size_t)r1 * C + colb]     = acc[mt][nt][2] + bi0;
                        rootout[(size_t)r1 * C + colb + 1] = acc[mt][nt][3] + bi1;
                    }
                }
            }
        }
    }
}

// ---------------------------------------------------------------------------
// Aggregation pass: one warp per dst node, 2 edges per iteration
// (half-warp per edge, 4 channels per lane via uint2), software pipelined.
// Odd counts handled by index clamping (duplicate edge is a no-op under max).
// mode 0: partial max -> out (raw, may be -inf)
// mode 1: combine with aggbuf, fix empty->0, + rootout, opt relu -> out
// ---------------------------------------------------------------------------
struct EdgeStage {
    uint2 m;
    uint2 v00, v01, v10, v11;
};

__device__ __forceinline__ void stage_load(const __half* __restrict__ xkl,
                                           const uint2* __restrict__ emeta,
                                           int eidx, EdgeStage& st) {
    st.m = emeta[eidx];
    unsigned w = st.m.x;
    int s   = w & 131071;
    int i0a = (w >> 17) & 7, i1a = (w >> 20) & 7;
    int dx  = (w >> 23) & 1, dy  = (w >> 24) & 1;
    int t00 = i0a + 5 * i1a;
    const __half* base = xkl + (size_t)s * (KK * C);
    st.v00 = *(const uint2*)(base + t00 * C);
    st.v01 = *(const uint2*)(base + (t00 + dx) * C);
    st.v10 = *(const uint2*)(base + (t00 + 5 * dy) * C);
    st.v11 = *(const uint2*)(base + (t00 + 5 * dy + dx) * C);
}

__device__ __forceinline__ void stage_consume(const EdgeStage& st, float4& macc) {
    float2 f = __half22float2(*(const __half2*)&st.m.y);
    float w00 = (1.0f - f.x) * (1.0f - f.y);
    float w01 = f.x * (1.0f - f.y);
    float w10 = (1.0f - f.x) * f.y;
    float w11 = f.x * f.y;
    const __half2* p00 = (const __half2*)&st.v00;
    const __half2* p01 = (const __half2*)&st.v01;
    const __half2* p10 = (const __half2*)&st.v10;
    const __half2* p11 = (const __half2*)&st.v11;
    float2 a0 = __half22float2(p00[0]), a1 = __half22float2(p00[1]);
    float2 b0 = __half22float2(p01[0]), b1 = __half22float2(p01[1]);
    float2 c0 = __half22float2(p10[0]), c1 = __half22float2(p10[1]);
    float2 d0 = __half22float2(p11[0]), d1 = __half22float2(p11[1]);
    float e0 = w00 * a0.x + w01 * b0.x + w10 * c0.x + w11 * d0.x;
    float e1 = w00 * a0.y + w01 * b0.y + w10 * c0.y + w11 * d0.y;
    float e2 = w00 * a1.x + w01 * b1.x + w10 * c1.x + w11 * d1.x;
    float e3 = w00 * a1.y + w01 * b1.y + w10 * c1.y + w11 * d1.y;
    macc.x = fmaxf(macc.x, e0);
    macc.y = fmaxf(macc.y, e1);
    macc.z = fmaxf(macc.z, e2);
    macc.w = fmaxf(macc.w, e3);
}

__global__ void agg_kernel(const __half* __restrict__ xk,
                           const uint2* __restrict__ emeta,
                           const int* __restrict__ off,
                           const int* __restrict__ deg,
                           const float* __restrict__ aggbuf,
                           const float* __restrict__ rootout,
                           float* __restrict__ out, int N,
                           int mode, int do_relu) {
    int node = blockIdx.x * 8 + (threadIdx.x >> 5);
    int lane = threadIdx.x & 31;
    if (node >= N) return;

    int beg = off[node];
    int cnt = deg[node];
    const int half = lane >> 4;
    const int c4 = (lane & 15) * 4;

    float4 macc = make_float4(-INFINITY, -INFINITY, -INFINITY, -INFINITY);

    if (cnt > 0) {
        const __half* xkl = xk + c4;
        int npair = (cnt + 1) >> 1;
        EdgeStage stA;
        stage_load(xkl, emeta, beg + min(half, cnt - 1), stA);
        for (int i = 1; i < npair; ++i) {
            EdgeStage stB;
            stage_load(xkl, emeta, beg + min(2 * i + half, cnt - 1), stB);
            stage_consume(stA, macc);
            stA = stB;
        }
        stage_consume(stA, macc);
    }

    // combine the two half-warps (same channels, different edges)
    macc.x = fmaxf(macc.x, __shfl_xor_sync(0xffffffffu, macc.x, 16));
    macc.y = fmaxf(macc.y, __shfl_xor_sync(0xffffffffu, macc.y, 16));
    macc.z = fmaxf(macc.z, __shfl_xor_sync(0xffffffffu, macc.z, 16));
    macc.w = fmaxf(macc.w, __shfl_xor_sync(0xffffffffu, macc.w, 16));

    if (lane < 16) {
        size_t o = (size_t)node * C + c4;
        if (mode == 0) {
            *(float4*)&out[o] = macc;
        } else {
            float4 p = *(const float4*)&aggbuf[o];
            macc.x = fmaxf(macc.x, p.x);
            macc.y = fmaxf(macc.y, p.y);
            macc.z = fmaxf(macc.z, p.z);
            macc.w = fmaxf(macc.w, p.w);
            if (!isfinite(macc.x)) macc.x = 0.0f;
            if (!isfinite(macc.y)) macc.y = 0.0f;
            if (!isfinite(macc.z)) macc.z = 0.0f;
            if (!isfinite(macc.w)) macc.w = 0.0f;
            float4 r = *(const float4*)&rootout[o];
            macc.x += r.x; macc.y += r.y; macc.z += r.z; macc.w += r.w;
            if (do_relu) {
                macc.x = fmaxf(macc.x, 0.0f);
                macc.y = fmaxf(macc.y, 0.0f);
                macc.z = fmaxf(macc.z, 0.0f);
                macc.w = fmaxf(macc.w, 0.0f);
            }
            *(float4*)&out[o] = macc;
        }
    }
}

// ---------------------------------------------------------------------------
extern "C" void kernel_launch(void* const* d_in, const int* in_sizes, int n_in,
                              void* d_out, int out_size) {
    const float* x      = (const float*)d_in[0];
    const int*   ei     = (const int*)  d_in[1];
    const float* pseudo = (const float*)d_in[2];
    const float* W1     = (const float*)d_in[3];
    const float* root1  = (const float*)d_in[4];
    const float* bias1  = (const float*)d_in[5];
    const float* W2     = (const float*)d_in[6];
    const float* root2  = (const float*)d_in[7];
    const float* bias2  = (const float*)d_in[8];

    const int N = in_sizes[0] / C;
    const int E = in_sizes[1] / 2;
    const int* src = ei;
    const int* dst = ei + E;

    __half* xk;
    float *h, *rootout, *aggbuf;
    uint2 *wf1, *wf2, *emeta;
    int *deg, *cur, *off, *offp, *bsum;
    cudaGetSymbolAddress((void**)&xk,      g_xk);
    cudaGetSymbolAddress((void**)&h,       g_h);
    cudaGetSymbolAddress((void**)&rootout, g_rootout);
    cudaGetSymbolAddress((void**)&aggbuf,  g_aggbuf);
    cudaGetSymbolAddress((void**)&wf1,     g_wf1);
    cudaGetSymbolAddress((void**)&wf2,     g_wf2);
    cudaGetSymbolAddress((void**)&deg,     g_deg);
    cudaGetSymbolAddress((void**)&cur,     g_cursor);
    cudaGetSymbolAddress((void**)&off,     g_off);
    cudaGetSymbolAddress((void**)&offp,    g_offp);
    cudaGetSymbolAddress((void**)&bsum,    g_bsum);
    cudaGetSymbolAddress((void**)&emeta,   g_emeta);

    const int total2N  = 2 * N;
    const int NB = (total2N + SCAN_B - 1) / SCAN_B;
    const int gemmBlocks = (N + 255) / 256;
    const int aggBlocks  = (N + 7) / 8;
    const int eBlocks    = (E + 255) / 256;
    const int wfTotal    = 26 * 4 * 8 * 32;

    // ---- setup (once, reused by both layers) ----
    cvt_w_kernel<<<(wfTotal + 255) / 256, 256>>>(W1, root1, wf1);
    cvt_w_kernel<<<(wfTotal + 255) / 256, 256>>>(W2, root2, wf2);
    zero_kernel<<<(total2N + 255) / 256, 256>>>(deg, cur, total2N);
    hist_kernel<<<eBlocks, 256>>>(dst, pseudo, deg, E, N);
    scan_local_kernel<<<NB, SCAN_B>>>(deg, offp, bsum, total2N);
    scan_bsum_kernel<<<1, 128>>>(bsum, NB);
    scan_add_kernel<<<(total2N + 255) / 256, 256>>>(offp, bsum, off, total2N);
    scatter_kernel<<<eBlocks, 256>>>(src, dst, pseudo, off, cur, emeta, E, N);

    // ---- Layer 1 ----
    gemm_xk_kernel<<<gemmBlocks, 256>>>(x, wf1, bias1, xk, rootout, N);
    agg_kernel<<<aggBlocks, 256>>>(xk, emeta, off,     deg,     aggbuf, rootout, aggbuf, N, 0, 0);
    agg_kernel<<<aggBlocks, 256>>>(xk, emeta, off + N, deg + N, aggbuf, rootout, h,      N, 1, 1);

    // ---- Layer 2 ----
    gemm_xk_kernel<<<gemmBlocks, 256>>>(h, wf2, bias2, xk, rootout, N);
    agg_kernel<<<aggBlocks, 256>>>(xk, emeta, off,     deg,     aggbuf, rootout, aggbuf, N, 0, 0);
    agg_kernel<<<aggBlocks, 256>>>(xk, emeta, off + N, deg + N, aggbuf, rootout, (float*)d_out, N, 1, 0);
}